// round 16
// baseline (speedup 1.0000x reference)
#include <cuda_runtime.h>
#include <cstdint>

// Embedding gather: out[token, :] = weight[input[token], :]
// input: [32768] int32, weight: [50257, 512] f32, out: [32768, 512] f32
//
// Measured-best structure (16.83-16.86us, reproduced 4x):
//   1. One warp per token row; 4 independent front-batched float4 loads
//      per thread (MLP=4) — covers DRAM latency without overrunning the
//      L1tex queue.
//   2. Block's 8 indices staged via ONE coalesced load into smem — kills
//      the serial idx-LDG -> weight-LDG dependent chain.
//
// This round completes the store-policy matrix: plain default writeback
// stores (st.global.wb, normal priority) — the only untested cell.
// Tested so far: .cs / evict_first (tie-best 16.83), .wt (20.0),
// evict_last (20.4). Default priority may allow PARTIAL writeback elision
// across graph replays (next replay overwrites still-resident dirty lines
// in place) without the hard L2 pinning that thrashed weight fills.

#define WARPS_PER_CTA 8

__global__ __launch_bounds__(WARPS_PER_CTA * 32) void embed_gather_wb(
    const int* __restrict__ idx,
    const float4* __restrict__ weight4,
    float4* __restrict__ out4,
    int n_tokens)
{
    __shared__ int s_rows[WARPS_PER_CTA];

    const int tid  = threadIdx.x;
    const int warp = tid >> 5;
    const int lane = tid & 31;
    const int base = blockIdx.x * WARPS_PER_CTA;

    // One coalesced load fetches all indices for this block.
    if (tid < WARPS_PER_CTA) {
        int t = base + tid;
        s_rows[tid] = (t < n_tokens) ? __ldg(idx + t) : 0;
    }
    __syncthreads();

    const int token = base + warp;
    if (token >= n_tokens) return;
    const int row = s_rows[warp];

    const float4* __restrict__ src = weight4 + (long long)row * 128 + lane;
    float4* __restrict__ dst       = out4    + (long long)token * 128 + lane;

    // 4 independent loads front-batched (MLP=4)
    float4 v0 = __ldg(src);
    float4 v1 = __ldg(src + 32);
    float4 v2 = __ldg(src + 64);
    float4 v3 = __ldg(src + 96);

    // Plain writeback stores (default L2 priority).
    dst[0]  = v0;
    dst[32] = v1;
    dst[64] = v2;
    dst[96] = v3;
}

extern "C" void kernel_launch(void* const* d_in, const int* in_sizes, int n_in,
                              void* d_out, int out_size) {
    const int*   idx    = (const int*)d_in[0];     // [8*4096] int32
    const float* weight = (const float*)d_in[1];   // [50257*512] f32
    float*       out    = (float*)d_out;

    int n_tokens = in_sizes[0];                    // 32768
    int blocks   = (n_tokens + WARPS_PER_CTA - 1) / WARPS_PER_CTA;  // 4096
    embed_gather_wb<<<blocks, WARPS_PER_CTA * 32>>>(
        idx, (const float4*)weight, (float4*)out, n_tokens);
}

// round 17
// speedup vs baseline: 1.1233x; 1.1233x over previous
#include <cuda_runtime.h>
#include <cstdint>

// Embedding gather: out[token, :] = weight[input[token], :]
// input: [32768] int32, weight: [50257, 512] f32, out: [32768, 512] f32
//
// FINAL kernel — measured-best at 16.83us, reproduced 4x across 16
// experiments. Steady-state: ~115MB compulsory traffic per graph replay
// (48MB unique weight rows + 67MB output writeback) at ~6.85TB/s
// sustained = ~85% of HBM spec. That is the practical roofline for this
// access pattern (random 2KB-row gather + streaming write, ~half the L2
// traffic paying the cross-die fabric hop).
//
// Load-bearing design decisions (each verified by a regressing or neutral
// counter-experiment):
//   1. One warp per token row, 4 independent front-batched float4 loads
//      per thread (MLP=4). MLP=8 neutral; MLP=1 costs +60%.
//   2. Block's 8 indices staged via ONE coalesced load into smem — removes
//      the serial idx-LDG (~600cyc) -> weight-LDG (~600cyc) chain; warps
//      read row ids via 29-cycle LDS.
//   3. __stcs evict-first streaming stores. Policy matrix: .cs/evict_first
//      16.83 (best) < default .wb 18.9 < .wt 20.0 < evict_last 20.4 —
//      demoting the output stream protects weight-row L2 residency.
// Also measured neutral/worse: TMA bulk staging (shared LTS cap with LDG),
// 256-bit v8 ops, persistent grid, dual LDG+TMA engines, L2 residency
// hints on loads, CTA shapes 128/512.

#define WARPS_PER_CTA 8

__global__ __launch_bounds__(WARPS_PER_CTA * 32) void embed_gather_smem_idx(
    const int* __restrict__ idx,
    const float4* __restrict__ weight4,
    float4* __restrict__ out4,
    int n_tokens)
{
    __shared__ int s_rows[WARPS_PER_CTA];

    const int tid  = threadIdx.x;
    const int warp = tid >> 5;
    const int lane = tid & 31;
    const int base = blockIdx.x * WARPS_PER_CTA;

    // One coalesced load fetches all indices for this block.
    if (tid < WARPS_PER_CTA) {
        int t = base + tid;
        s_rows[tid] = (t < n_tokens) ? __ldg(idx + t) : 0;
    }
    __syncthreads();

    const int token = base + warp;
    if (token >= n_tokens) return;
    const int row = s_rows[warp];

    const float4* __restrict__ src = weight4 + (long long)row * 128 + lane;
    float4* __restrict__ dst       = out4    + (long long)token * 128 + lane;

    // 4 independent loads front-batched (MLP=4)
    float4 v0 = __ldg(src);
    float4 v1 = __ldg(src + 32);
    float4 v2 = __ldg(src + 64);
    float4 v3 = __ldg(src + 96);

    // Evict-first streaming writeback (verified-best store policy).
    __stcs(dst,      v0);
    __stcs(dst + 32, v1);
    __stcs(dst + 64, v2);
    __stcs(dst + 96, v3);
}

extern "C" void kernel_launch(void* const* d_in, const int* in_sizes, int n_in,
                              void* d_out, int out_size) {
    const int*   idx    = (const int*)d_in[0];     // [8*4096] int32
    const float* weight = (const float*)d_in[1];   // [50257*512] f32
    float*       out    = (float*)d_out;

    int n_tokens = in_sizes[0];                    // 32768
    int blocks   = (n_tokens + WARPS_PER_CTA - 1) / WARPS_PER_CTA;  // 4096
    embed_gather_smem_idx<<<blocks, WARPS_PER_CTA * 32>>>(
        idx, (const float4*)weight, (float4*)out, n_tokens);
}